// round 11
// baseline (speedup 1.0000x reference)
#include <cuda_runtime.h>

// NonMaximaSuppression3d: x (4,4,32,256,256) fp32.
// out = x where x strictly exceeds all 26 neighbors; zero elsewhere (borders zero).
//
// R6 re-land (previous round died to container infra, kernel never measured)
// + reg slim: the h-1 slot only needs {Q, rmC}, not the full per-row state.
//
// Design recap:
//  - Each warp: 128 contiguous w (float4/lane), slides along h, fixed d.
//  - Separable maxes: Q = rowmax(max(plane d-1, d+1)), rmC = rowmax(center),
//    wex = in-row exclusion max. m26 = max(Q(h-1..h+1), rmC(h+-1), wex(h)).
//    Center never enters m26 -> strict 26-neighbor compare is exact.
//  - 2 output rows per iteration: 6 front-batched LDG.128 (MLP), shared
//    max(Q_h, Q_{h+1}) term, halved shuffle/rowmax work for off-planes.
//  - w-borders folded into +-inf bias; __launch_bounds__(128,6) for occupancy.

namespace {

constexpr int Dd = 32;
constexpr int Hh = 256;
constexpr int Ww = 256;
constexpr int PLANE = Hh * Ww;
constexpr int ROWS = 32;   // output rows per thread (even)

__device__ __forceinline__ float ninf() { return __int_as_float(0xff800000u); }
__device__ __forceinline__ float pinf() { return __int_as_float(0x7f800000u); }
__device__ __forceinline__ float fmax3(float a, float b, float c) {
    return fmaxf(a, fmaxf(b, c));
}
__device__ __forceinline__ float4 f4max(float4 a, float4 b) {
    return make_float4(fmaxf(a.x, b.x), fmaxf(a.y, b.y),
                       fmaxf(a.z, b.z), fmaxf(a.w, b.w));
}

// Raw loads for one row of all 3 planes (+ per-warp edge scalars, meaningful
// in exactly one lane per warp; -inf elsewhere).
struct Ld { float4 m, c, p; float em, ec, ep; };

__device__ __forceinline__ Ld load_row(const float* __restrict__ pm,
                                       const float* __restrict__ pc,
                                       const float* __restrict__ pp,
                                       int rn, int w0, bool rv, int ew)
{
    Ld L;
    const float ni = ninf();
    L.m = L.c = L.p = make_float4(ni, ni, ni, ni);
    L.em = L.ec = L.ep = ni;
    if (rv) {
        const float* rm_ = pm + rn * Ww;
        const float* rc_ = pc + rn * Ww;
        const float* rp_ = pp + rn * Ww;
        L.m = *reinterpret_cast<const float4*>(rm_ + w0);
        L.c = *reinterpret_cast<const float4*>(rc_ + w0);
        L.p = *reinterpret_cast<const float4*>(rp_ + w0);
        if (ew >= 0) {
            L.em = __ldg(rm_ + ew);
            L.ec = __ldg(rc_ + ew);
            L.ep = __ldg(rp_ + ew);
        }
    }
    return L;
}

// Full per-row reduced state (rows h, h+1, h+2 need all of it).
struct Red { float4 Q, rmC, wex, xc; };
// Slim state for the h-1 slot (only Q, rmC survive the slide).
struct RedS { float4 Q, rmC; };

__device__ __forceinline__ Red reduce_row(const Ld& L, int lane)
{
    Red R;
    // Off-planes: combine first, then ONE shuffle pair + ONE rowmax.
    const float4 cm = f4max(L.m, L.p);
    const float  ecm = fmaxf(L.em, L.ep);
    float l = __shfl_up_sync(0xffffffffu, cm.w, 1);
    float r = __shfl_down_sync(0xffffffffu, cm.x, 1);
    if (lane == 0)  l = ecm;
    if (lane == 31) r = ecm;
    R.Q.x = fmax3(l,    cm.x, cm.y);
    R.Q.y = fmax3(cm.x, cm.y, cm.z);
    R.Q.z = fmax3(cm.y, cm.z, cm.w);
    R.Q.w = fmax3(cm.z, cm.w, r);

    // Center plane: rowmax + w-exclusion from one shuffle pair.
    float lc = __shfl_up_sync(0xffffffffu, L.c.w, 1);
    float rc = __shfl_down_sync(0xffffffffu, L.c.x, 1);
    if (lane == 0)  lc = L.ec;
    if (lane == 31) rc = L.ec;
    R.rmC.x = fmax3(lc,    L.c.x, L.c.y);
    R.rmC.y = fmax3(L.c.x, L.c.y, L.c.z);
    R.rmC.z = fmax3(L.c.y, L.c.z, L.c.w);
    R.rmC.w = fmax3(L.c.z, L.c.w, rc);
    R.wex.x = fmaxf(lc,    L.c.y);
    R.wex.y = fmaxf(L.c.x, L.c.z);
    R.wex.z = fmaxf(L.c.y, L.c.w);
    R.wex.w = fmaxf(L.c.z, rc);
    R.xc = L.c;
    return R;
}

} // namespace

extern "C" __global__ void __launch_bounds__(128, 6)
nms3d_kernel(const float* __restrict__ x, float* __restrict__ out)
{
    const int lane  = threadIdx.x;
    const int d     = blockIdx.x >> 1;
    const int wside = blockIdx.x & 1;
    const int w0    = (wside * 32 + lane) * 4;            // 0..252
    const int hs    = (blockIdx.y * blockDim.y + threadIdx.y) * ROWS;
    const long slab = (long)blockIdx.z * (long)(Dd * PLANE);

    float* op = out + slab + (long)d * PLANE + w0;

    // Border planes: zero fill (output is poisoned, must be written).
    if (d == 0 || d == Dd - 1) {
        const float4 z = make_float4(0.f, 0.f, 0.f, 0.f);
        #pragma unroll 8
        for (int h = hs; h < hs + ROWS; ++h)
            *reinterpret_cast<float4*>(op + h * Ww) = z;
        return;
    }

    const float* pm = x + slab + (long)(d - 1) * PLANE;
    const float* pc = pm + PLANE;
    const float* pp = pc + PLANE;

    // Per-warp edge scalar index (exactly one lane per warp has a valid one).
    int ew = -1;
    if (lane == 0  && w0 > 0)       ew = w0 - 1;
    if (lane == 31 && w0 + 4 < Ww)  ew = w0 + 4;

    // w-border bias: +inf in the border component forces the compare to fail.
    const float biasL = (lane == 0  && w0 == 0)      ? pinf() : ninf();
    const float biasR = (lane == 31 && w0 == Ww - 4) ? pinf() : ninf();

    // Warm-up: rows hs-1 (slim), hs (full).
    RedS A;
    {
        Red t = reduce_row(load_row(pm, pc, pp, hs - 1, w0, hs > 0, ew), lane);
        A.Q = t.Q;  A.rmC = t.rmC;
    }
    Red B = reduce_row(load_row(pm, pc, pp, hs, w0, true, ew), lane);

    #pragma unroll 2
    for (int h = hs; h < hs + ROWS; h += 2) {
        // Batch all loads for rows h+1, h+2 up front (6 LDG.128).
        // h+1 <= hs+31 <= 255: always valid, no predicate needed.
        Ld L1 = load_row(pm, pc, pp, h + 1, w0, true,       ew);
        Ld L2 = load_row(pm, pc, pp, h + 2, w0, h + 2 < Hh, ew);

        Red C  = reduce_row(L1, lane);
        Red Dr = reduce_row(L2, lane);

        // Shared middle term for both emitted rows.
        const float4 t = f4max(B.Q, C.Q);

        // Row h: 26-max = Q(h-1), Q(h), Q(h+1), rmC(h-1), rmC(h+1), wex(h).
        float4 ma = f4max(f4max(A.Q, t), f4max(f4max(A.rmC, C.rmC), B.wex));
        ma.x = fmaxf(ma.x, biasL);  ma.w = fmaxf(ma.w, biasR);
        // Row h+1: Q(h), Q(h+1), Q(h+2), rmC(h), rmC(h+2), wex(h+1).
        float4 mb = f4max(f4max(t, Dr.Q), f4max(f4max(B.rmC, Dr.rmC), C.wex));
        mb.x = fmaxf(mb.x, biasL);  mb.w = fmaxf(mb.w, biasR);

        const bool hva = (h >= 1);           // only h==0 is a border row here
        const bool hvb = (h + 1 <= Hh - 2);  // only h+1==255 is a border row

        float4 oa, ob;
        oa.x = (hva && B.xc.x > ma.x) ? B.xc.x : 0.f;
        oa.y = (hva && B.xc.y > ma.y) ? B.xc.y : 0.f;
        oa.z = (hva && B.xc.z > ma.z) ? B.xc.z : 0.f;
        oa.w = (hva && B.xc.w > ma.w) ? B.xc.w : 0.f;
        ob.x = (hvb && C.xc.x > mb.x) ? C.xc.x : 0.f;
        ob.y = (hvb && C.xc.y > mb.y) ? C.xc.y : 0.f;
        ob.z = (hvb && C.xc.z > mb.z) ? C.xc.z : 0.f;
        ob.w = (hvb && C.xc.w > mb.w) ? C.xc.w : 0.f;

        *reinterpret_cast<float4*>(op + h * Ww)       = oa;
        *reinterpret_cast<float4*>(op + (h + 1) * Ww) = ob;

        // Slide by 2 (A keeps only what row h+2's emission will read).
        A.Q = C.Q;  A.rmC = C.rmC;
        B = Dr;
    }
}

extern "C" void kernel_launch(void* const* d_in, const int* in_sizes, int n_in,
                              void* d_out, int out_size)
{
    const float* x = (const float*)d_in[0];
    float* out = (float*)d_out;
    (void)in_sizes; (void)n_in; (void)out_size;

    // block: 32 lanes (x4 floats = 128 w) x 4 h-strips = 128 threads
    // grid:  (32 d x 2 w-sides) x 2 h-chunks x 16 (b*ch) slabs = 2048 blocks
    dim3 block(32, 4, 1);
    dim3 grid(Dd * 2, Hh / (ROWS * 4), 16);
    nms3d_kernel<<<grid, block>>>(x, out);
}

// round 13
// speedup vs baseline: 1.2357x; 1.2357x over previous
#include <cuda_runtime.h>

// NonMaximaSuppression3d: x (4,4,32,256,256) fp32.
// out = x where x strictly exceeds all 26 neighbors; zero elsewhere (borders zero).
//
// R12 = R5's software pipeline (the load->use distance of one full iteration
// was the real performance source; R6 removed it and regressed) + R6's cheaper
// reduce (off-planes combined BEFORE rowmax; +-inf border bias; slim h-1 slot).
//
//  - Each warp: 128 contiguous w (float4/lane), slides along h, fixed d.
//  - m26 = max(Q(h-1..h+1), rmC(h-1), rmC(h+1), wex(h)),
//    Q = rowmax(max(plane d-1, plane d+1)), rmC = rowmax(center),
//    wex = in-row exclusion. Center never enters m26 -> strict compare exact.
//  - Pipeline: loads for row h+2 issue at loop top; row h+1 (loaded last
//    iteration) is reduced; row h is emitted.

namespace {

constexpr int Dd = 32;
constexpr int Hh = 256;
constexpr int Ww = 256;
constexpr int PLANE = Hh * Ww;
constexpr int ROWS = 32;   // output rows per thread

__device__ __forceinline__ float ninf() { return __int_as_float(0xff800000u); }
__device__ __forceinline__ float pinf() { return __int_as_float(0x7f800000u); }
__device__ __forceinline__ float fmax3(float a, float b, float c) {
    return fmaxf(a, fmaxf(b, c));
}
__device__ __forceinline__ float4 f4max(float4 a, float4 b) {
    return make_float4(fmaxf(a.x, b.x), fmaxf(a.y, b.y),
                       fmaxf(a.z, b.z), fmaxf(a.w, b.w));
}

// Raw loads for one row of all 3 planes (+ per-warp edge scalars, meaningful
// in exactly one lane per warp; -inf elsewhere / when row invalid).
struct Ld { float4 m, c, p; float em, ec, ep; };

__device__ __forceinline__ Ld load_row(const float* __restrict__ pm,
                                       const float* __restrict__ pc,
                                       const float* __restrict__ pp,
                                       int rn, int w0, bool rv, int ew)
{
    Ld L;
    const float ni = ninf();
    L.m = L.c = L.p = make_float4(ni, ni, ni, ni);
    L.em = L.ec = L.ep = ni;
    if (rv) {
        const float* rm_ = pm + rn * Ww;
        const float* rc_ = pc + rn * Ww;
        const float* rp_ = pp + rn * Ww;
        L.m = *reinterpret_cast<const float4*>(rm_ + w0);
        L.c = *reinterpret_cast<const float4*>(rc_ + w0);
        L.p = *reinterpret_cast<const float4*>(rp_ + w0);
        if (ew >= 0) {
            L.em = __ldg(rm_ + ew);
            L.ec = __ldg(rc_ + ew);
            L.ep = __ldg(rp_ + ew);
        }
    }
    return L;
}

struct Red  { float4 Q, rmC, wex, xc; };  // full per-row reduced state
struct RedS { float4 Q, rmC; };           // slim state for the h-1 slot

__device__ __forceinline__ Red reduce_row(const Ld& L, int lane)
{
    Red R;
    // Off-planes: combine first, then ONE shuffle pair + ONE rowmax.
    const float4 cm  = f4max(L.m, L.p);
    const float  ecm = fmaxf(L.em, L.ep);
    float l = __shfl_up_sync(0xffffffffu, cm.w, 1);
    float r = __shfl_down_sync(0xffffffffu, cm.x, 1);
    if (lane == 0)  l = ecm;
    if (lane == 31) r = ecm;
    R.Q.x = fmax3(l,    cm.x, cm.y);
    R.Q.y = fmax3(cm.x, cm.y, cm.z);
    R.Q.z = fmax3(cm.y, cm.z, cm.w);
    R.Q.w = fmax3(cm.z, cm.w, r);

    // Center plane: rowmax + w-exclusion from one shuffle pair.
    float lc = __shfl_up_sync(0xffffffffu, L.c.w, 1);
    float rc = __shfl_down_sync(0xffffffffu, L.c.x, 1);
    if (lane == 0)  lc = L.ec;
    if (lane == 31) rc = L.ec;
    R.rmC.x = fmax3(lc,    L.c.x, L.c.y);
    R.rmC.y = fmax3(L.c.x, L.c.y, L.c.z);
    R.rmC.z = fmax3(L.c.y, L.c.z, L.c.w);
    R.rmC.w = fmax3(L.c.z, L.c.w, rc);
    R.wex.x = fmaxf(lc,    L.c.y);
    R.wex.y = fmaxf(L.c.x, L.c.z);
    R.wex.z = fmaxf(L.c.y, L.c.w);
    R.wex.w = fmaxf(L.c.z, rc);
    R.xc = L.c;
    return R;
}

} // namespace

extern "C" __global__ void __launch_bounds__(128)
nms3d_kernel(const float* __restrict__ x, float* __restrict__ out)
{
    const int lane  = threadIdx.x;
    const int d     = blockIdx.x >> 1;
    const int wside = blockIdx.x & 1;
    const int w0    = (wside * 32 + lane) * 4;            // 0..252
    const int hs    = (blockIdx.y * blockDim.y + threadIdx.y) * ROWS;
    const long slab = (long)blockIdx.z * (long)(Dd * PLANE);

    float* op = out + slab + (long)d * PLANE + w0;

    // Border planes: zero fill (output is poisoned, must be written).
    if (d == 0 || d == Dd - 1) {
        const float4 z = make_float4(0.f, 0.f, 0.f, 0.f);
        #pragma unroll 8
        for (int h = hs; h < hs + ROWS; ++h)
            *reinterpret_cast<float4*>(op + h * Ww) = z;
        return;
    }

    const float* pm = x + slab + (long)(d - 1) * PLANE;
    const float* pc = pm + PLANE;
    const float* pp = pc + PLANE;

    // Per-warp edge scalar index (exactly one lane per warp has a valid one).
    int ew = -1;
    if (lane == 0  && w0 > 0)       ew = w0 - 1;
    if (lane == 31 && w0 + 4 < Ww)  ew = w0 + 4;

    // w-border bias: +inf in the border component forces the compare to fail.
    const float biasL = (lane == 0  && w0 == 0)      ? pinf() : ninf();
    const float biasR = (lane == 31 && w0 == Ww - 4) ? pinf() : ninf();

    // Warm-up: rows hs-1 (slim), hs (full); prime pipeline with row hs+1 loads.
    RedS A;
    {
        Red t = reduce_row(load_row(pm, pc, pp, hs - 1, w0, hs > 0, ew), lane);
        A.Q = t.Q;  A.rmC = t.rmC;
    }
    Red B = reduce_row(load_row(pm, pc, pp, hs, w0, true, ew), lane);
    Ld CUR = load_row(pm, pc, pp, hs + 1, w0, true, ew);  // hs+1 <= 225 < Hh

    #pragma unroll 4
    for (int h = hs; h < hs + ROWS; ++h) {
        // Issue next row's loads FIRST (row h+2) — consumed next iteration.
        const bool ld2 = (h + 1 < hs + ROWS) && (h + 2 < Hh);
        Ld NXT = load_row(pm, pc, pp, h + 2, w0, ld2, ew);

        // Reduce CUR = row h+1 (its loads were issued last iteration).
        Red C = reduce_row(CUR, lane);

        // Emit row h: m26 = Q(h-1), Q(h), Q(h+1), rmC(h-1), rmC(h+1), wex(h).
        float4 m26 = f4max(f4max(A.Q, f4max(B.Q, C.Q)),
                           f4max(f4max(A.rmC, C.rmC), B.wex));
        m26.x = fmaxf(m26.x, biasL);
        m26.w = fmaxf(m26.w, biasR);

        const bool hv = (h >= 1) && (h <= Hh - 2);
        float4 o;
        o.x = (hv && B.xc.x > m26.x) ? B.xc.x : 0.f;
        o.y = (hv && B.xc.y > m26.y) ? B.xc.y : 0.f;
        o.z = (hv && B.xc.z > m26.z) ? B.xc.z : 0.f;
        o.w = (hv && B.xc.w > m26.w) ? B.xc.w : 0.f;
        *reinterpret_cast<float4*>(op + h * Ww) = o;

        // Slide.
        A.Q = B.Q;  A.rmC = B.rmC;
        B = C;
        CUR = NXT;
    }
}

extern "C" void kernel_launch(void* const* d_in, const int* in_sizes, int n_in,
                              void* d_out, int out_size)
{
    const float* x = (const float*)d_in[0];
    float* out = (float*)d_out;
    (void)in_sizes; (void)n_in; (void)out_size;

    // block: 32 lanes (x4 floats = 128 w) x 4 h-strips = 128 threads
    // grid:  (32 d x 2 w-sides) x 2 h-chunks x 16 (b*ch) slabs = 2048 blocks
    dim3 block(32, 4, 1);
    dim3 grid(Dd * 2, Hh / (ROWS * 4), 16);
    nms3d_kernel<<<grid, block>>>(x, out);
}